// round 16
// baseline (speedup 1.0000x reference)
#include <cuda_runtime.h>
#include <cuda_fp16.h>
#include <stdint.h>
#include <math.h>

#define HIDDEN   1536
#define NHEADS   8
#define HDIM     192
#define BATCH    8
#define SEQ      8192
#define M_TOTAL  (BATCH * SEQ)          // 65536
#define WIN      13
#define SOFTCAPF 50.0f
#define QSCALE   (0.07216878364870323f / 0.6931471805599453f)
#define LOGINC   (9.210340371976184 / 767.0)

// ---------------- scratch (device globals) ----------------
__device__ __half g_a_hi[(size_t)M_TOTAL * HIDDEN];
__device__ __half g_b_hi[(size_t)3 * HIDDEN * HIDDEN];   // [z][n][k] (transposed)
__device__ float g_q[(size_t)M_TOTAL * HIDDEN];
__device__ float g_k[(size_t)M_TOTAL * HIDDEN];
__device__ float g_v[(size_t)M_TOTAL * HIDDEN];
__device__ float g_sin[WIN * HIDDEN];

__device__ __forceinline__ uint32_t smem_u32(const void* p) {
    uint32_t a;
    asm("{ .reg .u64 t; cvta.to.shared.u64 t, %1; cvt.u32.u64 %0, t; }" : "=r"(a) : "l"(p));
    return a;
}

// ---------------- GEMM config (R14, unchanged) ----------------
#define BM 128
#define BN 128
#define BK 32
#define NCHUNK (HIDDEN / BK)     // 48
#define NSTAGE 3
#define APITCH 80                // 32 halves + 8 pad -> conflict-free ldsm, 16B-aligned
#define S_AH  0
#define S_BH  (BM * APITCH)               // 10240
#define STAGE_SZ (S_BH + BN * APITCH)     // 20480
#define SMEM_SZ (NSTAGE * STAGE_SZ)       // 61440 -> 3 CTAs/SM

__device__ __forceinline__ void cpa16(uint32_t dst, const void* src) {
    asm volatile("cp.async.cg.shared.global [%0], [%1], 16;" :: "r"(dst), "l"(src) : "memory");
}
__device__ __forceinline__ void ldsm_x4(uint32_t* r, uint32_t addr) {
    asm volatile("ldmatrix.sync.aligned.m8n8.x4.shared.b16 {%0,%1,%2,%3}, [%4];"
        : "=r"(r[0]), "=r"(r[1]), "=r"(r[2]), "=r"(r[3]) : "r"(addr));
}
__device__ __forceinline__ void mma16816(float* d, const uint32_t* a, uint32_t b0, uint32_t b1) {
    asm volatile(
        "mma.sync.aligned.m16n8k16.row.col.f32.f16.f16.f32 "
        "{%0,%1,%2,%3}, {%4,%5,%6,%7}, {%8,%9}, {%0,%1,%2,%3};"
        : "+f"(d[0]), "+f"(d[1]), "+f"(d[2]), "+f"(d[3])
        : "r"(a[0]), "r"(a[1]), "r"(a[2]), "r"(a[3]), "r"(b0), "r"(b1));
}

__device__ __forceinline__ void issue_chunk(uint32_t sb, int stage, int m0, int n0, int k0,
                                            const __half* Bh, int tid) {
    uint32_t s0 = sb + stage * STAGE_SZ;
    #pragma unroll
    for (int t = 0; t < 2; t++) {
        int idx = tid + t * 256;
        int r = idx >> 2, c = idx & 3;
        uint32_t so = (uint32_t)(r * APITCH + c * 16);
        size_t ga = (size_t)(m0 + r) * HIDDEN + k0 + c * 8;
        cpa16(s0 + S_AH + so, (const void*)(g_a_hi + ga));
        size_t gb = (size_t)(n0 + r) * HIDDEN + k0 + c * 8;
        cpa16(s0 + S_BH + so, (const void*)(Bh + gb));
    }
    asm volatile("cp.async.commit_group;" ::: "memory");
}

__global__ void __launch_bounds__(256, 3) hmma_gemm(const float* __restrict__ pds) {
    extern __shared__ char smem[];
    const uint32_t sb = smem_u32(smem);
    const int tid = threadIdx.x;
    const int wid = tid >> 5;
    const int lane = tid & 31;
    const int wm = wid & 1;      // 2 warps in M (64 rows each)
    const int wn = wid >> 1;     // 4 warps in N (32 cols each)
    const int z = blockIdx.z;
    const int m0 = blockIdx.y * BM;
    const int n0 = blockIdx.x * BN;

    const __half* Bh = g_b_hi + (size_t)z * HIDDEN * HIDDEN;
    float* Cout = (z == 0) ? g_q : (z == 1) ? g_k : g_v;

    float acc[4][4][4];
    #pragma unroll
    for (int i = 0; i < 4; i++)
        #pragma unroll
        for (int j = 0; j < 4; j++)
            #pragma unroll
            for (int e = 0; e < 4; e++) acc[i][j][e] = 0.0f;

    issue_chunk(sb, 0, m0, n0, 0, Bh, tid);
    issue_chunk(sb, 1, m0, n0, BK, Bh, tid);

    const uint32_t a_row_off = (uint32_t)((wm * 64 + (lane & 15)) * APITCH + (lane >> 4) * 16);
    const uint32_t b_row_off = (uint32_t)((wn * 32 + lane) * APITCH);

    int stage = 0;
    for (int c = 0; c < NCHUNK; c++) {
        if (c + 1 < NCHUNK) asm volatile("cp.async.wait_group 1;" ::: "memory");
        else                asm volatile("cp.async.wait_group 0;" ::: "memory");
        __syncthreads();

        if (c + 2 < NCHUNK) {
            int ns = stage + 2; if (ns >= NSTAGE) ns -= NSTAGE;
            issue_chunk(sb, ns, m0, n0, (c + 2) * BK, Bh, tid);
        }

        const uint32_t s0 = sb + stage * STAGE_SZ;
        const uint32_t abase = s0 + S_AH + a_row_off;
        const uint32_t bbase = s0 + S_BH + b_row_off;
        #pragma unroll
        for (int ks = 0; ks < 2; ks++) {
            uint32_t b0[4], b1[4];
            ldsm_x4(b0, bbase + (uint32_t)(ks * 32));
            ldsm_x4(b1, bbase + (uint32_t)(ks * 32 + 16));
            uint32_t a[4][4];
            #pragma unroll
            for (int i = 0; i < 4; i++)
                ldsm_x4(a[i], abase + (uint32_t)(i * 16 * APITCH + ks * 32));
            #pragma unroll
            for (int i = 0; i < 4; i++)
                #pragma unroll
                for (int j = 0; j < 4; j++)
                    mma16816(acc[i][j], a[i], b0[j], b1[j]);
        }
        if (++stage >= NSTAGE) stage = 0;
    }

    // ---- epilogue (fp32, full-sector float2 stores) ----
    float sc[4][2];
    #pragma unroll
    for (int j = 0; j < 4; j++) {
        #pragma unroll
        for (int e = 0; e < 2; e++) {
            if (z == 0) {
                int col = n0 + wn * 32 + j * 8 + 2 * (lane & 3) + e;
                sc[j][e] = QSCALE * log1pf(expf(pds[col % HDIM]));
            } else sc[j][e] = 1.0f;
        }
    }
    #pragma unroll
    for (int i = 0; i < 4; i++) {
        const int mrow = m0 + wm * 64 + i * 16 + (lane >> 2);
        #pragma unroll
        for (int j = 0; j < 4; j++) {
            const int ncol = n0 + wn * 32 + j * 8 + 2 * (lane & 3);
            float2 v0 = make_float2(acc[i][j][0] * sc[j][0], acc[i][j][1] * sc[j][1]);
            float2 v1 = make_float2(acc[i][j][2] * sc[j][0], acc[i][j][3] * sc[j][1]);
            *(float2*)&Cout[(size_t)mrow * HIDDEN + ncol] = v0;
            *(float2*)&Cout[(size_t)(mrow + 8) * HIDDEN + ncol] = v1;
        }
    }
}

// ---------------- prep: A -> fp16 ----------------
__global__ void __launch_bounds__(256) prep_a(const float* __restrict__ hs) {
    size_t i = ((size_t)blockIdx.x * 256 + threadIdx.x) * 4;
    float4 v = *(const float4*)&hs[i];
    union { __half b[4]; uint2 u; } ph;
    ph.b[0] = __float2half_rn(v.x);
    ph.b[1] = __float2half_rn(v.y);
    ph.b[2] = __float2half_rn(v.z);
    ph.b[3] = __float2half_rn(v.w);
    *(uint2*)&g_a_hi[i] = ph.u;
}

// ---------------- prep: W -> transposed fp16 ----------------
__global__ void __launch_bounds__(256) prep_w(const float* __restrict__ Wq,
                                              const float* __restrict__ Wk,
                                              const float* __restrict__ Wv) {
    __shared__ float t[32][33];
    const int z = blockIdx.z;
    const float* W = (z == 0) ? Wq : (z == 1) ? Wk : Wv;
    const int k0 = blockIdx.x * 32, n0 = blockIdx.y * 32;
    const int tx = threadIdx.x, ty = threadIdx.y;  // (32, 8)
    #pragma unroll
    for (int i = 0; i < 4; i++)
        t[ty + i * 8][tx] = W[(size_t)(k0 + ty + i * 8) * HIDDEN + n0 + tx];
    __syncthreads();
    #pragma unroll
    for (int i = 0; i < 4; i++) {
        float x = t[tx][ty + i * 8];
        size_t o = ((size_t)z * HIDDEN + n0 + ty + i * 8) * HIDDEN + k0 + tx;
        g_b_hi[o] = __float2half_rn(x);
    }
}

// ---------------- sin embedding ----------------
__global__ void __launch_bounds__(128) sin_emb_kernel(const float* __restrict__ w_pos) {
    __shared__ float emb[HIDDEN];
    const int f = blockIdx.x;
    const float posv = -(float)f;
    for (int i = threadIdx.x; i < HIDDEN / 2; i += 128) {
        float s = posv * expf(-(float)i * (float)LOGINC);
        emb[i] = sinf(s);
        emb[i + HIDDEN / 2] = cosf(s);
    }
    __syncthreads();
    const int o = blockIdx.y * 128 + threadIdx.x;
    float acc = 0.0f;
    #pragma unroll 8
    for (int i = 0; i < HIDDEN; i++)
        acc += emb[i] * w_pos[(size_t)i * HIDDEN + o];
    g_sin[f * HIDDEN + o] = acc;
}

// ---------------- tiled attention (window = 13, fp32) ----------------
#define TT  32                   // tokens per block
#define CTX (TT + 12)            // 44 k/v rows staged
#define ATT_SK   0
#define ATT_SV   (CTX * HDIM)                 // floats
#define ATT_SSIN (2 * CTX * HDIM)
#define ATT_SVAL (2 * CTX * HDIM + WIN * HDIM)  // bytes offset in floats*4
#define ATT_SMEM ((2 * CTX * HDIM + WIN * HDIM) * 4 + CTX + 64)

__global__ void __launch_bounds__(256, 2) attn_kernel(const unsigned char* __restrict__ mask,
                                                      float* __restrict__ out) {
    extern __shared__ float sm[];
    float* sk = sm + ATT_SK;
    float* sv = sm + ATT_SV;
    float* ss = sm + ATT_SSIN;
    unsigned char* sval = (unsigned char*)(sm + ATT_SVAL);

    const int t0 = blockIdx.x * TT;
    const int n  = blockIdx.y;
    const int b  = blockIdx.z;
    const int tid = threadIdx.x;

    if (tid < CTX) {
        int jt = t0 - 12 + tid;
        sval[tid] = (jt >= 0) && (mask[b * SEQ + jt] == 0);
    }
    // sin rows for this head: 13 x 192 floats = 624 float4
    for (int i = tid; i < WIN * HDIM / 4; i += 256) {
        int f = i / (HDIM / 4), c = i % (HDIM / 4);
        ((float4*)ss)[i] = *(const float4*)&g_sin[f * HIDDEN + n * HDIM + c * 4];
    }
    // k/v rows: 44 x 192 floats = 2112 float4 each
    for (int i = tid; i < CTX * HDIM / 4; i += 256) {
        int r = i / (HDIM / 4), c = i % (HDIM / 4);
        int jt = t0 - 12 + r;
        float4 kv = make_float4(0.f, 0.f, 0.f, 0.f), vv = kv;
        if (jt >= 0) {
            size_t base = (size_t)(b * SEQ + jt) * HIDDEN + n * HDIM + c * 4;
            kv = *(const float4*)&g_k[base];
            vv = *(const float4*)&g_v[base];
        }
        ((float4*)sk)[i] = kv;
        ((float4*)sv)[i] = vv;
    }
    __syncthreads();

    const int wid = tid >> 5;
    const int lane = tid & 31;

    #pragma unroll
    for (int it = 0; it < TT / 8; it++) {
        const int tl = wid + it * 8;            // local t (0..31)
        const size_t rowq = (size_t)(b * SEQ + t0 + tl) * HIDDEN + n * HDIM;

        // lane owns float2 slots i*32+lane (dims 2*(i*32+lane), +1), i=0..2
        float2 ql[3];
        #pragma unroll
        for (int i = 0; i < 3; i++)
            ql[i] = *(const float2*)&g_q[rowq + 2 * (i * 32 + lane)];

        float lg[WIN];
        unsigned valid = 0u;
        #pragma unroll
        for (int f = 0; f < WIN; f++) {
            const int r = tl + f;               // 0..43
            const float2* kk = (const float2*)(sk + r * HDIM);
            const float2* sp = (const float2*)(ss + f * HDIM);
            float dot = 0.0f;
            #pragma unroll
            for (int i = 0; i < 3; i++) {
                float2 kv = kk[i * 32 + lane];
                float2 se = sp[i * 32 + lane];
                dot = fmaf(ql[i].x, kv.x + se.x, dot);
                dot = fmaf(ql[i].y, kv.y + se.y, dot);
            }
            #pragma unroll
            for (int off = 16; off > 0; off >>= 1)
                dot += __shfl_xor_sync(0xFFFFFFFFu, dot, off);
            lg[f] = tanhf(dot * (1.0f / SOFTCAPF)) * SOFTCAPF;
            if (sval[r]) valid |= (1u << f);
        }

        float mx = -3.4e38f;
        #pragma unroll
        for (int f = 0; f < WIN; f++)
            if (valid & (1u << f)) mx = fmaxf(mx, lg[f]);

        float sum = 0.0f;
        #pragma unroll
        for (int f = 0; f < WIN; f++) {
            float p = (valid & (1u << f)) ? expf(lg[f] - mx) : 0.0f;
            lg[f] = p;
            sum += p;
        }
        const float inv = (sum > 0.0f) ? (1.0f / sum) : 0.0f;

        float2 oacc[3] = {{0.f, 0.f}, {0.f, 0.f}, {0.f, 0.f}};
        #pragma unroll
        for (int f = 0; f < WIN; f++) {
            if (lg[f] != 0.0f) {
                const float2* vv = (const float2*)(sv + (tl + f) * HDIM);
                const float p = lg[f];
                #pragma unroll
                for (int i = 0; i < 3; i++) {
                    float2 w = vv[i * 32 + lane];
                    oacc[i].x = fmaf(p, w.x, oacc[i].x);
                    oacc[i].y = fmaf(p, w.y, oacc[i].y);
                }
            }
        }
        #pragma unroll
        for (int i = 0; i < 3; i++)
            *(float2*)&out[rowq + 2 * (i * 32 + lane)] =
                make_float2(oacc[i].x * inv, oacc[i].y * inv);
    }
}

// ============================================================
extern "C" void kernel_launch(void* const* d_in, const int* in_sizes, int n_in,
                              void* d_out, int out_size) {
    const float* hs           = (const float*)d_in[0];
    const unsigned char* mask = (const unsigned char*)d_in[1];
    const float* w_q          = (const float*)d_in[2];
    const float* w_k          = (const float*)d_in[3];
    const float* w_v          = (const float*)d_in[4];
    const float* w_pos        = (const float*)d_in[5];
    const float* pds          = (const float*)d_in[6];
    float* out                = (float*)d_out;

    cudaFuncSetAttribute(hmma_gemm, cudaFuncAttributeMaxDynamicSharedMemorySize, SMEM_SZ);
    cudaFuncSetAttribute(attn_kernel, cudaFuncAttributeMaxDynamicSharedMemorySize, ATT_SMEM);

    prep_a<<<(int)(((size_t)M_TOTAL * HIDDEN) / 4 / 256), 256>>>(hs);
    prep_w<<<dim3(48, 48, 3), dim3(32, 8)>>>(w_q, w_k, w_v);
    sin_emb_kernel<<<dim3(WIN, HIDDEN / 128), 128>>>(w_pos);

    hmma_gemm<<<dim3(HIDDEN / BN, M_TOTAL / BM, 3), 256, SMEM_SZ>>>(pds);

    attn_kernel<<<dim3(SEQ / TT, NHEADS, BATCH), 256, ATT_SMEM>>>(mask, out);
}

// round 17
// speedup vs baseline: 1.6180x; 1.6180x over previous
#include <cuda_runtime.h>
#include <cuda_fp16.h>
#include <stdint.h>
#include <math.h>

#define HIDDEN   1536
#define NHEADS   8
#define HDIM     192
#define BATCH    8
#define SEQ      8192
#define M_TOTAL  (BATCH * SEQ)          // 65536
#define WIN      13
#define SOFTCAPF 50.0f
#define QSCALE   (0.07216878364870323f / 0.6931471805599453f)
#define LOGINC   (9.210340371976184 / 767.0)

// ---------------- scratch (device globals) ----------------
__device__ __half g_a_hi[(size_t)M_TOTAL * HIDDEN];
__device__ __half g_b_hi[(size_t)3 * HIDDEN * HIDDEN];   // [z][n][k] (transposed)
__device__ float g_q[(size_t)M_TOTAL * HIDDEN];
__device__ float g_k[(size_t)M_TOTAL * HIDDEN];
__device__ float g_v[(size_t)M_TOTAL * HIDDEN];
__device__ float g_sin[WIN * HIDDEN];

__device__ __forceinline__ uint32_t smem_u32(const void* p) {
    uint32_t a;
    asm("{ .reg .u64 t; cvta.to.shared.u64 t, %1; cvt.u32.u64 %0, t; }" : "=r"(a) : "l"(p));
    return a;
}

// ---------------- GEMM config (R14, byte-identical — host-speed control) ----------------
#define BM 128
#define BN 128
#define BK 32
#define NCHUNK (HIDDEN / BK)     // 48
#define NSTAGE 3
#define APITCH 80                // 32 halves + 8 pad -> conflict-free ldsm, 16B-aligned
#define S_AH  0
#define S_BH  (BM * APITCH)               // 10240
#define STAGE_SZ (S_BH + BN * APITCH)     // 20480
#define SMEM_SZ (NSTAGE * STAGE_SZ)       // 61440 -> 3 CTAs/SM

__device__ __forceinline__ void cpa16(uint32_t dst, const void* src) {
    asm volatile("cp.async.cg.shared.global [%0], [%1], 16;" :: "r"(dst), "l"(src) : "memory");
}
__device__ __forceinline__ void ldsm_x4(uint32_t* r, uint32_t addr) {
    asm volatile("ldmatrix.sync.aligned.m8n8.x4.shared.b16 {%0,%1,%2,%3}, [%4];"
        : "=r"(r[0]), "=r"(r[1]), "=r"(r[2]), "=r"(r[3]) : "r"(addr));
}
__device__ __forceinline__ void mma16816(float* d, const uint32_t* a, uint32_t b0, uint32_t b1) {
    asm volatile(
        "mma.sync.aligned.m16n8k16.row.col.f32.f16.f16.f32 "
        "{%0,%1,%2,%3}, {%4,%5,%6,%7}, {%8,%9}, {%0,%1,%2,%3};"
        : "+f"(d[0]), "+f"(d[1]), "+f"(d[2]), "+f"(d[3])
        : "r"(a[0]), "r"(a[1]), "r"(a[2]), "r"(a[3]), "r"(b0), "r"(b1));
}

__device__ __forceinline__ void issue_chunk(uint32_t sb, int stage, int m0, int n0, int k0,
                                            const __half* Bh, int tid) {
    uint32_t s0 = sb + stage * STAGE_SZ;
    #pragma unroll
    for (int t = 0; t < 2; t++) {
        int idx = tid + t * 256;
        int r = idx >> 2, c = idx & 3;
        uint32_t so = (uint32_t)(r * APITCH + c * 16);
        size_t ga = (size_t)(m0 + r) * HIDDEN + k0 + c * 8;
        cpa16(s0 + S_AH + so, (const void*)(g_a_hi + ga));
        size_t gb = (size_t)(n0 + r) * HIDDEN + k0 + c * 8;
        cpa16(s0 + S_BH + so, (const void*)(Bh + gb));
    }
    asm volatile("cp.async.commit_group;" ::: "memory");
}

__global__ void __launch_bounds__(256, 3) hmma_gemm(const float* __restrict__ pds) {
    extern __shared__ char smem[];
    const uint32_t sb = smem_u32(smem);
    const int tid = threadIdx.x;
    const int wid = tid >> 5;
    const int lane = tid & 31;
    const int wm = wid & 1;      // 2 warps in M (64 rows each)
    const int wn = wid >> 1;     // 4 warps in N (32 cols each)
    const int z = blockIdx.z;
    const int m0 = blockIdx.y * BM;
    const int n0 = blockIdx.x * BN;

    const __half* Bh = g_b_hi + (size_t)z * HIDDEN * HIDDEN;
    float* Cout = (z == 0) ? g_q : (z == 1) ? g_k : g_v;

    float acc[4][4][4];
    #pragma unroll
    for (int i = 0; i < 4; i++)
        #pragma unroll
        for (int j = 0; j < 4; j++)
            #pragma unroll
            for (int e = 0; e < 4; e++) acc[i][j][e] = 0.0f;

    issue_chunk(sb, 0, m0, n0, 0, Bh, tid);
    issue_chunk(sb, 1, m0, n0, BK, Bh, tid);

    const uint32_t a_row_off = (uint32_t)((wm * 64 + (lane & 15)) * APITCH + (lane >> 4) * 16);
    const uint32_t b_row_off = (uint32_t)((wn * 32 + lane) * APITCH);

    int stage = 0;
    for (int c = 0; c < NCHUNK; c++) {
        if (c + 1 < NCHUNK) asm volatile("cp.async.wait_group 1;" ::: "memory");
        else                asm volatile("cp.async.wait_group 0;" ::: "memory");
        __syncthreads();

        if (c + 2 < NCHUNK) {
            int ns = stage + 2; if (ns >= NSTAGE) ns -= NSTAGE;
            issue_chunk(sb, ns, m0, n0, (c + 2) * BK, Bh, tid);
        }

        const uint32_t s0 = sb + stage * STAGE_SZ;
        const uint32_t abase = s0 + S_AH + a_row_off;
        const uint32_t bbase = s0 + S_BH + b_row_off;
        #pragma unroll
        for (int ks = 0; ks < 2; ks++) {
            uint32_t b0[4], b1[4];
            ldsm_x4(b0, bbase + (uint32_t)(ks * 32));
            ldsm_x4(b1, bbase + (uint32_t)(ks * 32 + 16));
            uint32_t a[4][4];
            #pragma unroll
            for (int i = 0; i < 4; i++)
                ldsm_x4(a[i], abase + (uint32_t)(i * 16 * APITCH + ks * 32));
            #pragma unroll
            for (int i = 0; i < 4; i++)
                #pragma unroll
                for (int j = 0; j < 4; j++)
                    mma16816(acc[i][j], a[i], b0[j], b1[j]);
        }
        if (++stage >= NSTAGE) stage = 0;
    }

    // ---- epilogue (fp32, full-sector float2 stores) ----
    float sc[4][2];
    #pragma unroll
    for (int j = 0; j < 4; j++) {
        #pragma unroll
        for (int e = 0; e < 2; e++) {
            if (z == 0) {
                int col = n0 + wn * 32 + j * 8 + 2 * (lane & 3) + e;
                sc[j][e] = QSCALE * log1pf(expf(pds[col % HDIM]));
            } else sc[j][e] = 1.0f;
        }
    }
    #pragma unroll
    for (int i = 0; i < 4; i++) {
        const int mrow = m0 + wm * 64 + i * 16 + (lane >> 2);
        #pragma unroll
        for (int j = 0; j < 4; j++) {
            const int ncol = n0 + wn * 32 + j * 8 + 2 * (lane & 3);
            float2 v0 = make_float2(acc[i][j][0] * sc[j][0], acc[i][j][1] * sc[j][1]);
            float2 v1 = make_float2(acc[i][j][2] * sc[j][0], acc[i][j][3] * sc[j][1]);
            *(float2*)&Cout[(size_t)mrow * HIDDEN + ncol] = v0;
            *(float2*)&Cout[(size_t)(mrow + 8) * HIDDEN + ncol] = v1;
        }
    }
}

// ---------------- prep: A -> fp16 ----------------
__global__ void __launch_bounds__(256) prep_a(const float* __restrict__ hs) {
    size_t i = ((size_t)blockIdx.x * 256 + threadIdx.x) * 4;
    float4 v = *(const float4*)&hs[i];
    union { __half b[4]; uint2 u; } ph;
    ph.b[0] = __float2half_rn(v.x);
    ph.b[1] = __float2half_rn(v.y);
    ph.b[2] = __float2half_rn(v.z);
    ph.b[3] = __float2half_rn(v.w);
    *(uint2*)&g_a_hi[i] = ph.u;
}

// ---------------- prep: W -> transposed fp16 ----------------
__global__ void __launch_bounds__(256) prep_w(const float* __restrict__ Wq,
                                              const float* __restrict__ Wk,
                                              const float* __restrict__ Wv) {
    __shared__ float t[32][33];
    const int z = blockIdx.z;
    const float* W = (z == 0) ? Wq : (z == 1) ? Wk : Wv;
    const int k0 = blockIdx.x * 32, n0 = blockIdx.y * 32;
    const int tx = threadIdx.x, ty = threadIdx.y;  // (32, 8)
    #pragma unroll
    for (int i = 0; i < 4; i++)
        t[ty + i * 8][tx] = W[(size_t)(k0 + ty + i * 8) * HIDDEN + n0 + tx];
    __syncthreads();
    #pragma unroll
    for (int i = 0; i < 4; i++) {
        float x = t[tx][ty + i * 8];
        size_t o = ((size_t)z * HIDDEN + n0 + ty + i * 8) * HIDDEN + k0 + tx;
        g_b_hi[o] = __float2half_rn(x);
    }
}

// ---------------- sin embedding ----------------
__global__ void __launch_bounds__(128) sin_emb_kernel(const float* __restrict__ w_pos) {
    __shared__ float emb[HIDDEN];
    const int f = blockIdx.x;
    const float posv = -(float)f;
    for (int i = threadIdx.x; i < HIDDEN / 2; i += 128) {
        float s = posv * expf(-(float)i * (float)LOGINC);
        emb[i] = sinf(s);
        emb[i + HIDDEN / 2] = cosf(s);
    }
    __syncthreads();
    const int o = blockIdx.y * 128 + threadIdx.x;
    float acc = 0.0f;
    #pragma unroll 8
    for (int i = 0; i < HIDDEN; i++)
        acc += emb[i] * w_pos[(size_t)i * HIDDEN + o];
    g_sin[f * HIDDEN + o] = acc;
}

// ---------------- attention (window = 13, fp32, R14 structure + __expf) ----------------
__global__ void __launch_bounds__(256) attn_kernel(const unsigned char* __restrict__ mask,
                                                   float* __restrict__ out) {
    const int warp = (blockIdx.x * blockDim.x + threadIdx.x) >> 5;
    const int lane = threadIdx.x & 31;
    const int n = warp & 7;
    const int t = (warp >> 3) & (SEQ - 1);
    const int b = warp >> 16;

    const size_t rowq = (size_t)(b * SEQ + t) * HIDDEN + n * HDIM;

    // lane owns float2 slots i*32+lane (dims 2*(i*32+lane), +1), i=0..2
    float2 ql[3];
    #pragma unroll
    for (int i = 0; i < 3; i++)
        ql[i] = *(const float2*)&g_q[rowq + 2 * (i * 32 + lane)];

    float lg[WIN];
    unsigned valid = 0u;

    #pragma unroll
    for (int f = 0; f < WIN; f++) {
        int jt = t - 12 + f;
        float dot = 0.0f;
        bool ok = (jt >= 0) && (mask[b * SEQ + jt] == 0);
        if (jt >= 0) {
            const float* kr = g_k + (size_t)(b * SEQ + jt) * HIDDEN + n * HDIM;
            const float* sbase = g_sin + f * HIDDEN + n * HDIM;
            #pragma unroll
            for (int i = 0; i < 3; i++) {
                float2 kv = *(const float2*)&kr[2 * (i * 32 + lane)];
                float2 sv = *(const float2*)&sbase[2 * (i * 32 + lane)];
                dot = fmaf(ql[i].x, kv.x + sv.x, dot);
                dot = fmaf(ql[i].y, kv.y + sv.y, dot);
            }
        }
        #pragma unroll
        for (int off = 16; off > 0; off >>= 1)
            dot += __shfl_xor_sync(0xFFFFFFFFu, dot, off);
        dot = tanhf(dot * (1.0f / SOFTCAPF)) * SOFTCAPF;
        lg[f] = dot;
        if (ok) valid |= (1u << f);
    }

    float mx = -3.4e38f;
    #pragma unroll
    for (int f = 0; f < WIN; f++)
        if (valid & (1u << f)) mx = fmaxf(mx, lg[f]);

    float sum = 0.0f;
    #pragma unroll
    for (int f = 0; f < WIN; f++) {
        float p = (valid & (1u << f)) ? __expf(lg[f] - mx) : 0.0f;
        lg[f] = p;
        sum += p;
    }
    float inv = (sum > 0.0f) ? (1.0f / sum) : 0.0f;

    float2 oacc[3] = {{0.f, 0.f}, {0.f, 0.f}, {0.f, 0.f}};
    #pragma unroll
    for (int f = 0; f < WIN; f++) {
        int jt = t - 12 + f;
        if (jt >= 0 && lg[f] != 0.0f) {
            const float* vr = g_v + (size_t)(b * SEQ + jt) * HIDDEN + n * HDIM;
            float p = lg[f];
            #pragma unroll
            for (int i = 0; i < 3; i++) {
                float2 vv = *(const float2*)&vr[2 * (i * 32 + lane)];
                oacc[i].x = fmaf(p, vv.x, oacc[i].x);
                oacc[i].y = fmaf(p, vv.y, oacc[i].y);
            }
        }
    }
    #pragma unroll
    for (int i = 0; i < 3; i++)
        *(float2*)&out[rowq + 2 * (i * 32 + lane)] =
            make_float2(oacc[i].x * inv, oacc[i].y * inv);
}

// ============================================================
extern "C" void kernel_launch(void* const* d_in, const int* in_sizes, int n_in,
                              void* d_out, int out_size) {
    const float* hs           = (const float*)d_in[0];
    const unsigned char* mask = (const unsigned char*)d_in[1];
    const float* w_q          = (const float*)d_in[2];
    const float* w_k          = (const float*)d_in[3];
    const float* w_v          = (const float*)d_in[4];
    const float* w_pos        = (const float*)d_in[5];
    const float* pds          = (const float*)d_in[6];
    float* out                = (float*)d_out;

    cudaFuncSetAttribute(hmma_gemm, cudaFuncAttributeMaxDynamicSharedMemorySize, SMEM_SZ);

    prep_a<<<(int)(((size_t)M_TOTAL * HIDDEN) / 4 / 256), 256>>>(hs);
    prep_w<<<dim3(48, 48, 3), dim3(32, 8)>>>(w_q, w_k, w_v);
    sin_emb_kernel<<<dim3(WIN, HIDDEN / 128), 128>>>(w_pos);

    hmma_gemm<<<dim3(HIDDEN / BN, M_TOTAL / BM, 3), 256, SMEM_SZ>>>(pds);

    attn_kernel<<<(BATCH * SEQ * NHEADS * 32) / 256, 256>>>(mask, out);
}